// round 1
// baseline (speedup 1.0000x reference)
#include <cuda_runtime.h>
#include <cstdint>

// ---------------------------------------------------------------------------
// DynamicConvBlock: fused 65-tap combined depthwise conv + ReLU + 1x1 conv.
//   x:(8,192,96,96) f32 -> out:(8,64,96,96) f32
// Stage 0: prep kernel folds {a, wk1d1, wk3d1, wk5d1, wk7d1, wk3d5, wk3d7}
//          into a per-channel-pair packed 65-tap table (float2: even/odd ch).
// Stage 1: conv kernel, 2 channels packed in f32x2, vertical register window.
// Stage 2: pointwise kernel, oc-pairs packed in f32x2, wp transposed in smem.
// ---------------------------------------------------------------------------

#define NB   8
#define NC   192
#define NCP  96          // channel pairs
#define NH   96
#define NW   96
#define HW   (NH*NW)     // 9216
#define NOC  64
#define TAPS 65
#define PROW 16          // output rows per thread in conv kernel

// scratch (device globals are the sanctioned scratch mechanism)
__device__ float2 g_wc[NCP * TAPS];                    // packed combined weights
__device__ float  g_mid[(size_t)NB * NC * HW];         // relu'd depthwise output (56.6 MB)

// ---- tap tables (section = one dx column; dy list per section) -------------
__device__ constexpr int SEC_DX[11]   = {-7,-5,-3,-2,-1, 0, 1, 2, 3, 5, 7};
__device__ constexpr int SEC_BASE[11] = {-7,-5,-3,-3,-3,-7,-3,-3,-3,-5,-7};  // min dy
__device__ constexpr int SEC_W[11]    = {30,26,22,22,22,30,22,22,22,26,30};  // window rows (P=16)
__device__ constexpr int SEC_N[11]    = { 3, 3, 7, 7, 7,11, 7, 7, 7, 3, 3};
__device__ constexpr int SEC_OFF[11]  = { 0, 3, 6,13,20,27,38,45,52,59,62};

__device__ constexpr int DY_FLAT[TAPS] = {
    -7,0,7,                      // dx=-7
    -5,0,5,                      // dx=-5
    -3,-2,-1,0,1,2,3,            // dx=-3
    -3,-2,-1,0,1,2,3,            // dx=-2
    -3,-2,-1,0,1,2,3,            // dx=-1
    -7,-5,-3,-2,-1,0,1,2,3,5,7,  // dx=0
    -3,-2,-1,0,1,2,3,            // dx=1
    -3,-2,-1,0,1,2,3,            // dx=2
    -3,-2,-1,0,1,2,3,            // dx=3
    -5,0,5,                      // dx=5
    -7,0,7                       // dx=7
};
__device__ constexpr int DX_FLAT[TAPS] = {
    -7,-7,-7,
    -5,-5,-5,
    -3,-3,-3,-3,-3,-3,-3,
    -2,-2,-2,-2,-2,-2,-2,
    -1,-1,-1,-1,-1,-1,-1,
     0, 0, 0, 0, 0, 0, 0, 0, 0, 0, 0,
     1, 1, 1, 1, 1, 1, 1,
     2, 2, 2, 2, 2, 2, 2,
     3, 3, 3, 3, 3, 3, 3,
     5, 5, 5,
     7, 7, 7
};

// ---- packed f32x2 helpers --------------------------------------------------
__device__ __forceinline__ unsigned long long fma2_(unsigned long long a,
                                                    unsigned long long b,
                                                    unsigned long long c) {
    unsigned long long d;
    asm("fma.rn.f32x2 %0, %1, %2, %3;" : "=l"(d) : "l"(a), "l"(b), "l"(c));
    return d;
}
__device__ __forceinline__ unsigned long long dup2_(float v) {
    unsigned long long d;
    asm("mov.b64 %0, {%1, %1};" : "=l"(d) : "f"(v));
    return d;
}
__device__ __forceinline__ float2 unpk2_(unsigned long long v) {
    float2 f;
    asm("mov.b64 {%0, %1}, %2;" : "=f"(f.x), "=f"(f.y) : "l"(v));
    return f;
}

// ---------------------------------------------------------------------------
// Stage 0: build combined 65-tap weights per channel (cross-correlation,
// matching jax.lax.conv_general_dilated).
// ---------------------------------------------------------------------------
__global__ void prep_kernel(const float* __restrict__ a,
                            const float* __restrict__ k1,
                            const float* __restrict__ k3,
                            const float* __restrict__ k5,
                            const float* __restrict__ k7,
                            const float* __restrict__ k3d5,
                            const float* __restrict__ k3d7) {
    int i = blockIdx.x * blockDim.x + threadIdx.x;
    if (i >= NC * TAPS) return;
    int c = i / TAPS, t = i % TAPS;
    int dy = DY_FLAT[t], dx = DX_FLAT[t];
    float w = 0.0f;
    if (abs(dy) <= 3 && abs(dx) <= 3) w += a[4] * k7[c * 49 + (dy + 3) * 7 + (dx + 3)];
    if (abs(dy) <= 2 && abs(dx) <= 2) w += a[3] * k5[c * 25 + (dy + 2) * 5 + (dx + 2)];
    if (abs(dy) <= 1 && abs(dx) <= 1) w += (a[2] + a[5]) * k3[c * 9 + (dy + 1) * 3 + (dx + 1)];
    if (dy == 0 && dx == 0)           w += a[0] + a[1] * k1[c];
    if ((dy == -5 || dy == 0 || dy == 5) && (dx == -5 || dx == 0 || dx == 5))
        w += a[6] * k3d5[c * 9 + (dy / 5 + 1) * 3 + (dx / 5 + 1)];
    if ((dy == -7 || dy == 0 || dy == 7) && (dx == -7 || dx == 0 || dx == 7))
        w += a[7] * k3d7[c * 9 + (dy / 7 + 1) * 3 + (dx / 7 + 1)];
    float* dst = reinterpret_cast<float*>(&g_wc[(c >> 1) * TAPS + t]);
    dst[c & 1] = w;
}

// ---------------------------------------------------------------------------
// Stage 1: depthwise conv + ReLU. One block = (batch, channel-pair, 16-row
// strip across full width). 96 threads, one image column each, 16 rows each.
// Data packed (ch_even, ch_odd) as f32x2 in smem and registers.
// ---------------------------------------------------------------------------
#define SM_ROWS 30
#define SM_PITCH 112   // float2 units, >= 110

__global__ void __launch_bounds__(96)
conv_kernel(const float* __restrict__ x) {
    __shared__ float2 sm[SM_ROWS][SM_PITCH];

    const int tid = threadIdx.x;                    // 0..95
    const int bc  = blockIdx.y;                     // b*96 + cp
    const int b   = bc / NCP;
    const int cp  = bc - b * NCP;
    const int c0  = cp * 2;
    const int h0  = blockIdx.x * PROW;              // 0,16,...,80

    // ---- load 30x110 halo tile for 2 channels (zero padded) ----
    const size_t xbase = ((size_t)b * NC + c0) * HW;
    for (int i = tid; i < SM_ROWS * 110; i += 96) {
        int r = i / 110, col = i - r * 110;
        int gy = h0 + r - 7, gx = col - 7;
        float2 v = make_float2(0.0f, 0.0f);
        if ((unsigned)gy < NH && (unsigned)gx < NW) {
            size_t o = xbase + (size_t)gy * NW + gx;
            v.x = x[o];
            v.y = x[o + HW];
        }
        sm[r][col] = v;
    }
    __syncthreads();

    const int col = tid + 7;                         // smem column of this thread
    const unsigned long long* wc =
        reinterpret_cast<const unsigned long long*>(g_wc) + cp * TAPS;

    unsigned long long acc[PROW];
#pragma unroll
    for (int p = 0; p < PROW; p++) acc[p] = 0ull;

#pragma unroll
    for (int s = 0; s < 11; s++) {
        const int dx  = SEC_DX[s];
        const int bse = SEC_BASE[s];
        const int wl  = SEC_W[s];
        const int nd  = SEC_N[s];
        const int off = SEC_OFF[s];
        const int cx  = col + dx;

        unsigned long long win[SM_ROWS];
#pragma unroll
        for (int i = 0; i < wl; i++)
            win[i] = *reinterpret_cast<const unsigned long long*>(&sm[bse + 7 + i][cx]);

#pragma unroll
        for (int j = 0; j < nd; j++) {
            const int dy = DY_FLAT[off + j];
            const unsigned long long w2 = __ldg(&wc[off + j]);
            const int o = dy - bse;
#pragma unroll
            for (int p = 0; p < PROW; p++)
                acc[p] = fma2_(win[o + p], w2, acc[p]);
        }
    }

    // ---- ReLU + store to g_mid (standard NCHW layout) ----
    float* m0 = g_mid + xbase + (size_t)h0 * NW + tid;
#pragma unroll
    for (int p = 0; p < PROW; p++) {
        float2 v = unpk2_(acc[p]);
        v.x = fmaxf(v.x, 0.0f);
        v.y = fmaxf(v.y, 0.0f);
        m0[(size_t)p * NW]      = v.x;
        m0[(size_t)p * NW + HW] = v.y;
    }
}

// ---------------------------------------------------------------------------
// Stage 2: pointwise 1x1 conv 192->64 as SIMT GEMM with f32x2 oc-pairs.
// Block = 256 threads = 64 pixel-groups (4 px each) x 4 oc-groups (16 oc each).
// wp transposed + oc-paired in smem (48 KB), broadcast LDS.64 in the hot loop.
// ---------------------------------------------------------------------------
__global__ void __launch_bounds__(256)
pointwise_kernel(const float* __restrict__ wp, float* __restrict__ out) {
    __shared__ float2 ws[NC * 32];                  // ws[c*32+j] = (wp[2j][c], wp[2j+1][c])

    const int tid = threadIdx.x;
    for (int i = tid; i < NC * 32; i += 256) {
        int c = i >> 5, j = i & 31;
        ws[i] = make_float2(wp[(2 * j) * NC + c], wp[(2 * j + 1) * NC + c]);
    }
    __syncthreads();

    const int pxg = tid & 63;
    const int ocg = tid >> 6;                       // uniform per warp
    const int pixglob = blockIdx.x * 256 + pxg * 4; // 256 | 9216 -> block in one batch
    const int b   = pixglob / HW;
    const int pix = pixglob - b * HW;

    const float* midb = g_mid + (size_t)b * NC * HW + pix;
    const unsigned long long* wbase =
        reinterpret_cast<const unsigned long long*>(ws) + ocg * 8;

    unsigned long long acc[4][8];
#pragma unroll
    for (int p = 0; p < 4; p++)
#pragma unroll
        for (int j = 0; j < 8; j++) acc[p][j] = 0ull;

#pragma unroll 2
    for (int c = 0; c < NC; c++) {
        float4 m = *reinterpret_cast<const float4*>(midb + (size_t)c * HW);
        unsigned long long m0 = dup2_(m.x), m1 = dup2_(m.y),
                           m2 = dup2_(m.z), m3 = dup2_(m.w);
        const unsigned long long* wr = wbase + c * 32;
#pragma unroll
        for (int j = 0; j < 8; j++) {
            unsigned long long w2 = wr[j];          // broadcast LDS.64
            acc[0][j] = fma2_(m0, w2, acc[0][j]);
            acc[1][j] = fma2_(m1, w2, acc[1][j]);
            acc[2][j] = fma2_(m2, w2, acc[2][j]);
            acc[3][j] = fma2_(m3, w2, acc[3][j]);
        }
    }

    float* ob = out + ((size_t)b * NOC + ocg * 16) * HW + pix;
#pragma unroll
    for (int j = 0; j < 8; j++) {
        float2 a0 = unpk2_(acc[0][j]), a1 = unpk2_(acc[1][j]);
        float2 a2 = unpk2_(acc[2][j]), a3 = unpk2_(acc[3][j]);
        float4 lo = make_float4(a0.x, a1.x, a2.x, a3.x);
        float4 hi = make_float4(a0.y, a1.y, a2.y, a3.y);
        *reinterpret_cast<float4*>(ob + (size_t)(2 * j) * HW)     = lo;
        *reinterpret_cast<float4*>(ob + (size_t)(2 * j + 1) * HW) = hi;
    }
}

// ---------------------------------------------------------------------------
extern "C" void kernel_launch(void* const* d_in, const int* in_sizes, int n_in,
                              void* d_out, int out_size) {
    const float* x    = (const float*)d_in[0];   // 8*192*96*96
    const float* a    = (const float*)d_in[1];   // 8
    const float* k1   = (const float*)d_in[2];   // 192*1*1*1
    const float* k3   = (const float*)d_in[3];   // 192*1*3*3
    const float* k5   = (const float*)d_in[4];   // 192*1*5*5
    const float* k7   = (const float*)d_in[5];   // 192*1*7*7
    const float* k3d5 = (const float*)d_in[6];   // 192*1*3*3
    const float* k3d7 = (const float*)d_in[7];   // 192*1*3*3
    const float* wp   = (const float*)d_in[8];   // 64*192*1*1
    float* out = (float*)d_out;

    prep_kernel<<<(NC * TAPS + 127) / 128, 128>>>(a, k1, k3, k5, k7, k3d5, k3d7);
    conv_kernel<<<dim3(NH / PROW, NB * NCP), 96>>>(x);
    pointwise_kernel<<<(NB * HW) / 256, 256>>>(wp, out);
}

// round 3
// speedup vs baseline: 2.6336x; 2.6336x over previous
#include <cuda_runtime.h>
#include <cstdint>

// ---------------------------------------------------------------------------
// DynamicConvBlock: fused 65-tap combined depthwise conv + ReLU + 1x1 conv.
//   x:(8,192,96,96) f32 -> out:(8,64,96,96) f32
// Stage 1: conv kernel. Folds the 7 weight tensors + a[] into a per-channel
//          65-tap table in smem, then streaming-window depthwise conv with
//          2 channels packed per f32x2 (FFMA2). One live input register.
// Stage 2: pointwise 1x1 conv 192->64, f32x2 oc-pairs, wp transposed in smem.
// ---------------------------------------------------------------------------

#define NB   8
#define NC   192
#define NCP  96          // channel pairs
#define NH   96
#define NW   96
#define HW   (NH*NW)     // 9216
#define NOC  64
#define TAPS 65
#define PROW 16          // output rows per thread in conv kernel

// scratch (device globals are the sanctioned scratch mechanism)
__device__ float g_mid[(size_t)NB * NC * HW];         // relu'd depthwise output (56.6 MB)

// ---- tap tables (section = one dx column; dy list per section) -------------
__device__ constexpr int SEC_DX[11]   = {-7,-5,-3,-2,-1, 0, 1, 2, 3, 5, 7};
__device__ constexpr int SEC_BASE[11] = {-7,-5,-3,-3,-3,-7,-3,-3,-3,-5,-7};  // min dy
__device__ constexpr int SEC_W[11]    = {30,26,22,22,22,30,22,22,22,26,30};  // window rows (PROW + span)
__device__ constexpr int SEC_N[11]    = { 3, 3, 7, 7, 7,11, 7, 7, 7, 3, 3};
__device__ constexpr int SEC_OFF[11]  = { 0, 3, 6,13,20,27,38,45,52,59,62};

__device__ constexpr int DY_FLAT[TAPS] = {
    -7,0,7,
    -5,0,5,
    -3,-2,-1,0,1,2,3,
    -3,-2,-1,0,1,2,3,
    -3,-2,-1,0,1,2,3,
    -7,-5,-3,-2,-1,0,1,2,3,5,7,
    -3,-2,-1,0,1,2,3,
    -3,-2,-1,0,1,2,3,
    -3,-2,-1,0,1,2,3,
    -5,0,5,
    -7,0,7
};
__device__ constexpr int DX_FLAT[TAPS] = {
    -7,-7,-7,
    -5,-5,-5,
    -3,-3,-3,-3,-3,-3,-3,
    -2,-2,-2,-2,-2,-2,-2,
    -1,-1,-1,-1,-1,-1,-1,
     0, 0, 0, 0, 0, 0, 0, 0, 0, 0, 0,
     1, 1, 1, 1, 1, 1, 1,
     2, 2, 2, 2, 2, 2, 2,
     3, 3, 3, 3, 3, 3, 3,
     5, 5, 5,
     7, 7, 7
};

// ---- packed f32x2 helpers --------------------------------------------------
__device__ __forceinline__ unsigned long long fma2_(unsigned long long a,
                                                    unsigned long long b,
                                                    unsigned long long c) {
    unsigned long long d;
    asm("fma.rn.f32x2 %0, %1, %2, %3;" : "=l"(d) : "l"(a), "l"(b), "l"(c));
    return d;
}
__device__ __forceinline__ unsigned long long dup2_(float v) {
    unsigned long long d;
    asm("mov.b64 %0, {%1, %1};" : "=l"(d) : "f"(v));
    return d;
}
__device__ __forceinline__ float2 unpk2_(unsigned long long v) {
    float2 f;
    asm("mov.b64 {%0, %1}, %2;" : "=f"(f.x), "=f"(f.y) : "l"(v));
    return f;
}

// ---- fold the 7 weight tensors + a[] into one 65-tap weight ----------------
__device__ __forceinline__ float fold_weight(int c, int t,
                                             const float* __restrict__ a,
                                             const float* __restrict__ k1,
                                             const float* __restrict__ k3,
                                             const float* __restrict__ k5,
                                             const float* __restrict__ k7,
                                             const float* __restrict__ k3d5,
                                             const float* __restrict__ k3d7) {
    int dy = DY_FLAT[t], dx = DX_FLAT[t];
    float w = 0.0f;
    if (abs(dy) <= 3 && abs(dx) <= 3) w += a[4] * k7[c * 49 + (dy + 3) * 7 + (dx + 3)];
    if (abs(dy) <= 2 && abs(dx) <= 2) w += a[3] * k5[c * 25 + (dy + 2) * 5 + (dx + 2)];
    if (abs(dy) <= 1 && abs(dx) <= 1) w += (a[2] + a[5]) * k3[c * 9 + (dy + 1) * 3 + (dx + 1)];
    if (dy == 0 && dx == 0)           w += a[0] + a[1] * k1[c];
    if ((dy == -5 || dy == 0 || dy == 5) && (dx == -5 || dx == 0 || dx == 5))
        w += a[6] * k3d5[c * 9 + (dy / 5 + 1) * 3 + (dx / 5 + 1)];
    if ((dy == -7 || dy == 0 || dy == 7) && (dx == -7 || dx == 0 || dx == 7))
        w += a[7] * k3d7[c * 9 + (dy / 7 + 1) * 3 + (dx / 7 + 1)];
    return w;
}

// ---------------------------------------------------------------------------
// Stage 1: depthwise conv + ReLU. One block = (batch, channel-pair, 16-row
// strip across full width). 96 threads, one image column each, 16 rows each.
// Streaming window: one live input register, scattered into 16 accumulators.
// ---------------------------------------------------------------------------
#define SM_ROWS 30
#define SM_PITCH 112   // float2 units, >= 110

__global__ void __launch_bounds__(96)
conv_kernel(const float* __restrict__ x,
            const float* __restrict__ a,
            const float* __restrict__ k1,
            const float* __restrict__ k3,
            const float* __restrict__ k5,
            const float* __restrict__ k7,
            const float* __restrict__ k3d5,
            const float* __restrict__ k3d7) {
    __shared__ float2 sm[SM_ROWS][SM_PITCH];
    __shared__ float2 sw[TAPS];

    const int tid = threadIdx.x;                    // 0..95
    const int bc  = blockIdx.y;                     // b*96 + cp
    const int b   = bc / NCP;
    const int cp  = bc - b * NCP;
    const int c0  = cp * 2;
    const int h0  = blockIdx.x * PROW;              // 0,16,...,80

    // ---- fold combined weights for this channel pair into smem ----
    for (int i = tid; i < 2 * TAPS; i += 96) {
        int t = i >> 1, half = i & 1;
        float w = fold_weight(c0 + half, t, a, k1, k3, k5, k7, k3d5, k3d7);
        reinterpret_cast<float*>(&sw[t])[half] = w;
    }

    // ---- load 30x110 halo tile for 2 channels (zero padded) ----
    const size_t xbase = ((size_t)b * NC + c0) * HW;
    for (int i = tid; i < SM_ROWS * 110; i += 96) {
        int r = i / 110, col = i - r * 110;
        int gy = h0 + r - 7, gx = col - 7;
        float2 v = make_float2(0.0f, 0.0f);
        if ((unsigned)gy < NH && (unsigned)gx < NW) {
            size_t o = xbase + (size_t)gy * NW + gx;
            v.x = x[o];
            v.y = x[o + HW];
        }
        sm[r][col] = v;
    }
    __syncthreads();

    const int col = tid + 7;                         // smem column of this thread
    const unsigned long long* swq = reinterpret_cast<const unsigned long long*>(sw);

    unsigned long long acc[PROW];
#pragma unroll
    for (int p = 0; p < PROW; p++) acc[p] = 0ull;

#pragma unroll
    for (int s = 0; s < 11; s++) {
        const int bse = SEC_BASE[s];
        const int wl  = SEC_W[s];
        const int nd  = SEC_N[s];
        const int off = SEC_OFF[s];
        const int cx  = col + SEC_DX[s];

        // preload this section's weights (<=11 pairs) into registers
        unsigned long long wv[11];
#pragma unroll
        for (int j = 0; j < nd; j++) wv[j] = swq[off + j];

        // stream window rows: one live input value at a time
#pragma unroll
        for (int i = 0; i < wl; i++) {
            unsigned long long v =
                *reinterpret_cast<const unsigned long long*>(&sm[bse + 7 + i][cx]);
#pragma unroll
            for (int j = 0; j < nd; j++) {
                const int p = i - (DY_FLAT[off + j] - bse);   // compile-time
                if (p >= 0 && p < PROW)
                    acc[p] = fma2_(v, wv[j], acc[p]);
            }
        }
    }

    // ---- ReLU + store to g_mid (standard NCHW layout) ----
    float* m0 = g_mid + xbase + (size_t)h0 * NW + tid;
#pragma unroll
    for (int p = 0; p < PROW; p++) {
        float2 v = unpk2_(acc[p]);
        v.x = fmaxf(v.x, 0.0f);
        v.y = fmaxf(v.y, 0.0f);
        m0[(size_t)p * NW]      = v.x;
        m0[(size_t)p * NW + HW] = v.y;
    }
}

// ---------------------------------------------------------------------------
// Stage 2: pointwise 1x1 conv 192->64 as SIMT GEMM with f32x2 oc-pairs.
// Block = 128 threads = 32 pixel-groups (4 px each) x 4 oc-groups (16 oc each).
// wp transposed + oc-paired in smem (48 KB), broadcast LDS.64 in the hot loop.
// c-loop unrolled x4 with grouped loads for MLP.
// ---------------------------------------------------------------------------
__global__ void __launch_bounds__(128)
pointwise_kernel(const float* __restrict__ wp, float* __restrict__ out) {
    __shared__ float2 ws[NC * 32];                  // ws[c*32+j] = (wp[2j][c], wp[2j+1][c])

    const int tid = threadIdx.x;
    for (int i = tid; i < NC * 32; i += 128) {
        int c = i >> 5, j = i & 31;
        ws[i] = make_float2(wp[(2 * j) * NC + c], wp[(2 * j + 1) * NC + c]);
    }
    __syncthreads();

    const int pxg = tid & 31;
    const int ocg = tid >> 5;                       // uniform per warp
    const int pixglob = blockIdx.x * 128 + pxg * 4; // 128 | 9216 -> block in one batch
    const int b   = pixglob / HW;
    const int pix = pixglob - b * HW;

    const float* midb = g_mid + (size_t)b * NC * HW + pix;
    const unsigned long long* wbase =
        reinterpret_cast<const unsigned long long*>(ws) + ocg * 8;

    unsigned long long acc[4][8];
#pragma unroll
    for (int p = 0; p < 4; p++)
#pragma unroll
        for (int j = 0; j < 8; j++) acc[p][j] = 0ull;

#pragma unroll 1
    for (int c = 0; c < NC; c += 4) {
        float4 m[4];
#pragma unroll
        for (int u = 0; u < 4; u++)
            m[u] = *reinterpret_cast<const float4*>(midb + (size_t)(c + u) * HW);

#pragma unroll
        for (int u = 0; u < 4; u++) {
            unsigned long long m0 = dup2_(m[u].x), m1 = dup2_(m[u].y),
                               m2 = dup2_(m[u].z), m3 = dup2_(m[u].w);
            const unsigned long long* wr = wbase + (c + u) * 32;
#pragma unroll
            for (int j = 0; j < 8; j++) {
                unsigned long long w2 = wr[j];      // broadcast LDS.64
                acc[0][j] = fma2_(m0, w2, acc[0][j]);
                acc[1][j] = fma2_(m1, w2, acc[1][j]);
                acc[2][j] = fma2_(m2, w2, acc[2][j]);
                acc[3][j] = fma2_(m3, w2, acc[3][j]);
            }
        }
    }

    float* ob = out + ((size_t)b * NOC + ocg * 16) * HW + pix;
#pragma unroll
    for (int j = 0; j < 8; j++) {
        float2 a0 = unpk2_(acc[0][j]), a1 = unpk2_(acc[1][j]);
        float2 a2 = unpk2_(acc[2][j]), a3 = unpk2_(acc[3][j]);
        float4 lo = make_float4(a0.x, a1.x, a2.x, a3.x);
        float4 hi = make_float4(a0.y, a1.y, a2.y, a3.y);
        *reinterpret_cast<float4*>(ob + (size_t)(2 * j) * HW)     = lo;
        *reinterpret_cast<float4*>(ob + (size_t)(2 * j + 1) * HW) = hi;
    }
}

// ---------------------------------------------------------------------------
extern "C" void kernel_launch(void* const* d_in, const int* in_sizes, int n_in,
                              void* d_out, int out_size) {
    const float* x    = (const float*)d_in[0];   // 8*192*96*96
    const float* a    = (const float*)d_in[1];   // 8
    const float* k1   = (const float*)d_in[2];   // 192*1*1*1
    const float* k3   = (const float*)d_in[3];   // 192*1*3*3
    const float* k5   = (const float*)d_in[4];   // 192*1*5*5
    const float* k7   = (const float*)d_in[5];   // 192*1*7*7
    const float* k3d5 = (const float*)d_in[6];   // 192*1*3*3
    const float* k3d7 = (const float*)d_in[7];   // 192*1*3*3
    const float* wp   = (const float*)d_in[8];   // 64*192*1*1
    float* out = (float*)d_out;

    conv_kernel<<<dim3(NH / PROW, NB * NCP), 96>>>(x, a, k1, k3, k5, k7, k3d5, k3d7);
    pointwise_kernel<<<(NB * HW) / 128, 128>>>(wp, out);
}